// round 14
// baseline (speedup 1.0000x reference)
#include <cuda_runtime.h>
#include <math.h>

// ---------------- problem constants ----------------
#define BATCH 64
#define TSEQ  256
#define INDIM 264
#define SU    512
#define NH    4
#define MSZ   32
#define NA    256
#define DB    256
#define COMBD 904
#define COMBP 1024
#define OUTD  1192
#define UPDD  424
#define HP    106

#define KSPLIT 4
#define KCH    256
#define KSUB   64
#define NCB    38
#define PARTW  1216

// raw upd offsets per head
#define OFF_S     0
#define OFF_JD    3
#define OFF_J     4
#define OFF_GAM   7
#define OFF_ER    8
#define OFF_AD    40
#define OFF_K     72
#define OFF_BETA  104
#define OFF_G     105

#define EPSV 1e-12f

#define MEMSZ (BATCH * MSZ * NA)
#define WTSZ  (BATCH * NH * NA)

// ---------------- device-global scratch ----------------
__device__ float g_Wt[PARTW * COMBP];
__device__ float g_bias[PARTW];
__device__ float g_comb[BATCH * COMBP];
__device__ float g_part[KSPLIT * BATCH * PARTW];
__device__ float g_wt[2 * WTSZ];        // double-buffered by step parity
__device__ float g_wtdyn[WTSZ];
__device__ float g_mem[2 * MEMSZ];      // double-buffered by step parity

__device__ __forceinline__ float sigm(float x) { return 1.0f / (1.0f + __expf(-x)); }
__device__ __forceinline__ float splus(float x) {
    return fmaxf(x, 0.0f) + log1pf(__expf(-fabsf(x)));
}

// packed f32x2 FMA: d = a*b + d (lane-wise on 2 floats in a 64-bit reg)
__device__ __forceinline__ void fma2(unsigned long long& d,
                                     unsigned long long a, unsigned long long b) {
    asm("fma.rn.f32x2 %0, %1, %2, %0;" : "+l"(d) : "l"(a), "l"(b));
}
__device__ __forceinline__ float f2sum(unsigned long long a) {
    float lo, hi;
    asm("mov.b64 {%0, %1}, %2;" : "=f"(lo), "=f"(hi) : "l"(a));
    return lo + hi;
}

// ---------------- weight repack ----------------
__global__ void pack_kernel(const float* __restrict__ Wo, const float* __restrict__ bo,
                            const float* __restrict__ Ws, const float* __restrict__ bs,
                            const float* __restrict__ Wu, const float* __restrict__ bu) {
    int idx = blockIdx.x * 256 + threadIdx.x;
    if (idx < PARTW * COMBP) {
        int j = idx >> 10;
        int k = idx & (COMBP - 1);
        float v = 0.0f;
        if (k < COMBD && j < OUTD) {
            if (j < DB)            v = Wo[k * DB + j];
            else if (j < DB + SU)  v = Ws[k * SU + (j - DB)];
            else                   v = Wu[k * UPDD + (j - DB - SU)];
        }
        g_Wt[idx] = v;
    }
    if (idx < PARTW) {
        g_bias[idx] = (idx >= OUTD) ? 0.0f
                    : (idx < DB) ? bo[idx]
                    : (idx < DB + SU) ? bs[idx - DB]
                    : bu[idx - DB - SU];
    }
}

// ---------------- init: reset carry (parity-0 buffers) + comb_0 ----------------
__global__ void init_kernel(const float* __restrict__ x) {
    int b = blockIdx.x, tid = threadIdx.x;
    for (int i = tid; i < NH * NA; i += 256) {
        float v = ((i & (NA - 1)) == 0) ? 1.0f : 0.0f;
        g_wt[b * NH * NA + i]    = v;
        g_wtdyn[b * NH * NA + i] = v;
    }
    for (int i = tid; i < MSZ * NA; i += 256) g_mem[b * MSZ * NA + i] = 0.01f;
    for (int i = tid; i < COMBP; i += 256) {
        float v;
        if (i < INDIM)            v = x[((size_t)b * TSEQ + 0) * INDIM + i];
        else if (i < INDIM + SU)  v = 1.0f;
        else if (i < COMBD)       v = 0.01f;
        else                      v = 0.0f;
        g_comb[b * COMBP + i] = v;
    }
}

// ---------------- GEMM (f32x2 packed): grid (38,4) = 152 CTAs = 1 wave ----------------
__global__ void __launch_bounds__(256) gemm_kernel() {
    __shared__ float cS[64][KSUB + 4];
    __shared__ float wS[32][KSUB + 4];

    int tid = threadIdx.x;
    int cb = blockIdx.x, ks = blockIdx.y;
    int j0 = cb * 32;
    int k0 = ks * KCH;
    int rq = tid >> 4, cp = tid & 15;
    int r0 = rq * 4;

    unsigned long long A00 = 0, A01 = 0, A10 = 0, A11 = 0;
    unsigned long long A20 = 0, A21 = 0, A30 = 0, A31 = 0;

    float4 cP[4], wP[2];
    {
        int kc = k0;
        #pragma unroll
        for (int s = 0; s < 4; s++) {
            int p = tid + s * 256;
            int r = p >> 4, k4 = p & 15;
            cP[s] = *(const float4*)&g_comb[r * COMBP + kc + 4 * k4];
        }
        #pragma unroll
        for (int s = 0; s < 2; s++) {
            int p = tid + s * 256;
            int jj = p >> 4, k4 = p & 15;
            wP[s] = *(const float4*)&g_Wt[(size_t)(j0 + jj) * COMBP + kc + 4 * k4];
        }
    }

    #pragma unroll 1
    for (int sub = 0; sub < KCH / KSUB; sub++) {
        #pragma unroll
        for (int s = 0; s < 4; s++) {
            int p = tid + s * 256;
            int r = p >> 4, k4 = p & 15;
            *(float4*)&cS[r][4 * k4] = cP[s];
        }
        #pragma unroll
        for (int s = 0; s < 2; s++) {
            int p = tid + s * 256;
            int jj = p >> 4, k4 = p & 15;
            *(float4*)&wS[jj][4 * k4] = wP[s];
        }
        __syncthreads();

        if (sub < KCH / KSUB - 1) {
            int kc = k0 + (sub + 1) * KSUB;
            #pragma unroll
            for (int s = 0; s < 4; s++) {
                int p = tid + s * 256;
                int r = p >> 4, k4 = p & 15;
                cP[s] = *(const float4*)&g_comb[r * COMBP + kc + 4 * k4];
            }
            #pragma unroll
            for (int s = 0; s < 2; s++) {
                int p = tid + s * 256;
                int jj = p >> 4, k4 = p & 15;
                wP[s] = *(const float4*)&g_Wt[(size_t)(j0 + jj) * COMBP + kc + 4 * k4];
            }
        }

        #pragma unroll 8
        for (int kk = 0; kk < KSUB; kk += 4) {
            ulonglong2 w0 = *(const ulonglong2*)&wS[cp][kk];
            ulonglong2 w1 = *(const ulonglong2*)&wS[cp + 16][kk];
            ulonglong2 q0 = *(const ulonglong2*)&cS[r0 + 0][kk];
            ulonglong2 q1 = *(const ulonglong2*)&cS[r0 + 1][kk];
            ulonglong2 q2 = *(const ulonglong2*)&cS[r0 + 2][kk];
            ulonglong2 q3 = *(const ulonglong2*)&cS[r0 + 3][kk];
            fma2(A00, q0.x, w0.x); fma2(A01, q0.x, w1.x);
            fma2(A10, q1.x, w0.x); fma2(A11, q1.x, w1.x);
            fma2(A20, q2.x, w0.x); fma2(A21, q2.x, w1.x);
            fma2(A30, q3.x, w0.x); fma2(A31, q3.x, w1.x);
            fma2(A00, q0.y, w0.y); fma2(A01, q0.y, w1.y);
            fma2(A10, q1.y, w0.y); fma2(A11, q1.y, w1.y);
            fma2(A20, q2.y, w0.y); fma2(A21, q2.y, w1.y);
            fma2(A30, q3.y, w0.y); fma2(A31, q3.y, w1.y);
        }
        __syncthreads();
    }

    float* pp = &g_part[(ks * BATCH) * PARTW];
    pp[(r0 + 0) * PARTW + j0 + cp]      = f2sum(A00);
    pp[(r0 + 0) * PARTW + j0 + cp + 16] = f2sum(A01);
    pp[(r0 + 1) * PARTW + j0 + cp]      = f2sum(A10);
    pp[(r0 + 1) * PARTW + j0 + cp + 16] = f2sum(A11);
    pp[(r0 + 2) * PARTW + j0 + cp]      = f2sum(A20);
    pp[(r0 + 2) * PARTW + j0 + cp + 16] = f2sum(A21);
    pp[(r0 + 3) * PARTW + j0 + cp]      = f2sum(A30);
    pp[(r0 + 3) * PARTW + j0 + cp + 16] = f2sum(A31);
}

// ---------------- update: combine + DWM cell; grid=256 (b,h), 256 thr ----------------
__global__ void __launch_bounds__(256) update_kernel(const float* __restrict__ x,
                                                     float* __restrict__ dout, int t) {
    __shared__ float memS[MSZ][260];    // conflict-free row & column access
    __shared__ float wtA[NH * NA];
    __shared__ float wgH[NA];
    __shared__ float wsS[NA];           // raw sharpened weights (pre-normalization)
    __shared__ float dynS[NA];          // old snapshot weights
    __shared__ float4 e4v[MSZ], a4v[MSZ];
    __shared__ float pKs[MSZ];
    __shared__ float scl[16];
    __shared__ float red[16];
    __shared__ float upS[HP + 2];

    int b = blockIdx.x >> 2, h = blockIdx.x & 3;
    int tid = threadIdx.x;
    int n = tid, lane = tid & 31, wid = tid >> 5;
    int par = t & 1;

    const float* P0 = &g_part[(0 * BATCH + b) * PARTW];
    const float* P1 = &g_part[(1 * BATCH + b) * PARTW];
    const float* P2 = &g_part[(2 * BATCH + b) * PARTW];
    const float* P3 = &g_part[(3 * BATCH + b) * PARTW];

    float dynOld = g_wtdyn[(b * NH + h) * NA + n];
    dynS[n] = dynOld;

    // ---- prefetch out/state partials into registers (consumed at tail) ----
    int jOut = 64 * h + tid;               // valid if tid < 64
    int jSt  = 256 + 128 * h + tid;        // valid if tid < 128
    float o0 = 0.f, o1 = 0.f, o2 = 0.f, o3 = 0.f, ob = 0.f;
    float s0 = 0.f, s1 = 0.f, s2 = 0.f, s3 = 0.f, sb = 0.f;
    if (tid < 64) {
        o0 = P0[jOut]; o1 = P1[jOut]; o2 = P2[jOut]; o3 = P3[jOut]; ob = g_bias[jOut];
    }
    if (tid < 128) {
        s0 = P0[jSt]; s1 = P1[jSt]; s2 = P2[jSt]; s3 = P3[jSt]; sb = g_bias[jSt];
    }

    // ---- load mem (8 f4/thread) and all-head wt from parity buffers ----
    const float4* memIn = (const float4*)(g_mem + par * MEMSZ + b * MSZ * NA);
    #pragma unroll
    for (int s = 0; s < 8; s++) {
        int p = tid + s * 256;
        int m = p >> 6, c4 = p & 63;
        *(float4*)&memS[m][4 * c4] = memIn[p];
    }
    *(float4*)&wtA[4 * tid] = ((const float4*)(g_wt + par * WTSZ + b * NH * NA))[tid];

    // ---- own-head raw params ----
    if (tid < HP) {
        int j = 768 + HP * h + tid;
        upS[tid] = P0[j] + P1[j] + P2[j] + P3[j] + g_bias[j];
    }
    // erase/add for ALL heads (needed by the shared memory write)
    {
        int hp = tid >> 6, idx = tid & 63;
        int j = 768 + HP * hp + OFF_ER + idx;
        float v = P0[j] + P1[j] + P2[j] + P3[j] + g_bias[j];
        if (idx < 32) ((float*)&e4v[idx])[hp] = sigm(v);
        else          ((float*)&a4v[idx - 32])[hp] = v;
    }
    __syncthreads();   // S1

    // ---- parse own-head params: khat in warp 0; scalars spread across warps ----
    if (tid < 32) {
        float kt = tanhf(upS[OFF_K + tid]);
        float ssk = kt * kt;
        #pragma unroll
        for (int o = 16; o; o >>= 1) ssk += __shfl_xor_sync(0xffffffffu, ssk, o);
        pKs[tid] = kt / (sqrtf(ssk) + EPSV);
    }
    {
        int q = -1;
        if (lane == 0)                 q = wid;        // 0..7
        else if (lane == 16 && wid < 2) q = 8 + wid;   // 8,9
        if (q >= 0) {
            float v;
            if (q < 3) {                 // shift softmax(softplus) component q
                float a0 = splus(upS[OFF_S + 0]), a1 = splus(upS[OFF_S + 1]), a2 = splus(upS[OFF_S + 2]);
                float mx = fmaxf(a0, fmaxf(a1, a2));
                float e0 = __expf(a0 - mx), e1 = __expf(a1 - mx), e2 = __expf(a2 - mx);
                float sel = (q == 0) ? e0 : (q == 1) ? e1 : e2;
                v = sel / (e0 + e1 + e2);
            } else if (q < 6) {          // jump softmax component q-3
                float j0r = upS[OFF_J + 0], j1r = upS[OFF_J + 1], j2r = upS[OFF_J + 2];
                float jm = fmaxf(j0r, fmaxf(j1r, j2r));
                float f0 = __expf(j0r - jm), f1 = __expf(j1r - jm), f2 = __expf(j2r - jm);
                float sel = (q == 3) ? f0 : (q == 4) ? f1 : f2;
                v = sel / (f0 + f1 + f2);
            } else if (q == 6) v = sigm(upS[OFF_JD]);
            else if (q == 7)   v = 1.0f + splus(upS[OFF_GAM]);
            else if (q == 8)   v = splus(upS[OFF_BETA]);
            else               v = sigm(upS[OFF_G]);
            scl[q] = v;
        }
    }

    // ---- memory write (erase, add) — duplicated in 4 head-CTAs; h==0 persists ----
    float4* memOut = (float4*)(g_mem + (par ^ 1) * MEMSZ + b * MSZ * NA);
    #pragma unroll
    for (int s = 0; s < 8; s++) {
        int p = tid + s * 256;
        int m = p >> 6, c4 = p & 63;
        float4 mv = *(const float4*)&memS[m][4 * c4];
        float4 e4 = e4v[m], a4 = a4v[m];
        float4 w0 = *(const float4*)&wtA[0 * 256 + 4 * c4];
        float4 w1 = *(const float4*)&wtA[1 * 256 + 4 * c4];
        float4 w2 = *(const float4*)&wtA[2 * 256 + 4 * c4];
        float4 w3 = *(const float4*)&wtA[3 * 256 + 4 * c4];
        #pragma unroll
        for (int i = 0; i < 4; i++) {
            float vv = (&mv.x)[i];
            float q0 = (&w0.x)[i], q1 = (&w1.x)[i], q2 = (&w2.x)[i], q3 = (&w3.x)[i];
            float prod = (1.0f - e4.x * q0) * (1.0f - e4.y * q1)
                       * (1.0f - e4.z * q2) * (1.0f - e4.w * q3);
            float addv = a4.x * q0 + a4.y * q1 + a4.z * q2 + a4.w * q3;
            (&mv.x)[i] = vv * prod + addv;
        }
        *(float4*)&memS[m][4 * c4] = mv;
        if (h == 0) memOut[p] = mv;
    }
    __syncthreads();   // S2

    // ---- content score: sc = beta * khat . memcol / ||memcol|| ----
    float beta = scl[8], g = scl[9];
    float ss = 0.0f, sc = 0.0f;
    #pragma unroll
    for (int m = 0; m < MSZ; m++) {
        float v = memS[m][n];
        ss = fmaf(v, v, ss);
        sc = fmaf(pKs[m], v, sc);
    }
    sc = sc * beta / (sqrtf(ss) + EPSV);

    // softmax shifted by beta (valid upper bound since cos <= 1)
    float e = __expf(sc - beta);
    float sv = e;
    #pragma unroll
    for (int o = 16; o; o >>= 1) sv += __shfl_xor_sync(0xffffffffu, sv, o);
    if (lane == 0) red[wid] = sv;

    // ---- R_dynOld[m] = sum_n dynOld[n]*mem[m][n] (hidden in softmax latency) ----
    float rdDyn;
    {
        int m = tid >> 3, s = tid & 7;
        float acc = 0.0f;
        #pragma unroll
        for (int i = 0; i < 32; i++) {
            int nn = s * 32 + ((i + m + 4 * s) & 31);
            acc = fmaf(dynS[nn], memS[m][nn], acc);
        }
        acc += __shfl_down_sync(0xffffffffu, acc, 4, 8);
        acc += __shfl_down_sync(0xffffffffu, acc, 2, 8);
        acc += __shfl_down_sync(0xffffffffu, acc, 1, 8);
        rdDyn = acc;    // valid on s==0 lanes
    }
    __syncthreads();   // S3
    float tot = red[0] + red[1] + red[2] + red[3] + red[4] + red[5] + red[6] + red[7];
    float wc = e / tot;
    float wOld = wtA[h * 256 + n];
    wgH[n] = fmaf(g, wc - wOld, wOld);
    __syncthreads();   // S4

    // ---- shift + sharpen (raw, normalization deferred) ----
    float wsraw = scl[0] * wgH[(n + NA - 1) & (NA - 1)]
                + scl[1] * wgH[n]
                + scl[2] * wgH[(n + 1) & (NA - 1)];
    wsraw = __expf(scl[7] * __logf(wsraw + EPSV));
    wsS[n] = wsraw;
    float sv2 = wsraw;
    #pragma unroll
    for (int o = 16; o; o >>= 1) sv2 += __shfl_xor_sync(0xffffffffu, sv2, o);
    if (lane == 0) red[8 + wid] = sv2;
    __syncthreads();   // S5
    float tot2 = red[8] + red[9] + red[10] + red[11] + red[12] + red[13] + red[14] + red[15];
    float invT2 = 1.0f / tot2;
    float ws = wsraw * invT2;

    // ---- snapshot + jump (stores only; not on the read path) ----
    float jd = scl[6];
    float dynNew = fmaf(jd, ws - dynOld, dynOld);
    g_wtdyn[(b * NH + h) * NA + n] = dynNew;
    float wnew = scl[3] * ws + scl[4] * dynNew + ((n == 0) ? scl[5] : 0.0f);
    g_wt[(par ^ 1) * WTSZ + (b * NH + h) * NA + n] = wnew;

    // ---- read via split einsums: read[m] = cA*R_wsraw[m] + cB*R_dyn[m] + j2*mem[m][0] ----
    {
        int m = tid >> 3, s = tid & 7;
        float acc = 0.0f;
        #pragma unroll
        for (int i = 0; i < 32; i++) {
            int nn = s * 32 + ((i + m + 4 * s) & 31);
            acc = fmaf(wsS[nn], memS[m][nn], acc);
        }
        acc += __shfl_down_sync(0xffffffffu, acc, 4, 8);
        acc += __shfl_down_sync(0xffffffffu, acc, 2, 8);
        acc += __shfl_down_sync(0xffffffffu, acc, 1, 8);
        if (s == 0) {
            float cA = (scl[3] + scl[4] * jd) * invT2;   // j0 + j1*jd, /tot2
            float cB = scl[4] * (1.0f - jd);             // j1*(1-jd)
            float rd = cA * acc + cB * rdDyn + scl[5] * memS[m][0];
            g_comb[b * COMBP + INDIM + SU + h * 32 + m] = rd;
        }
    }

    // ---- tail: out/state combine (prefetched at top) + x_{t+1} copy ----
    if (tid < 64)
        dout[((size_t)b * TSEQ + t) * DB + jOut] = sigm(o0 + o1 + o2 + o3 + ob);
    if (tid < 128)
        g_comb[b * COMBP + jSt + 8] = sigm(s0 + s1 + s2 + s3 + sb);
    if (h == 0 && tid < 66) {
        float4 xv = *(const float4*)&x[((size_t)b * TSEQ + (t + 1)) * INDIM + 4 * tid];
        *(float4*)&g_comb[b * COMBP + 4 * tid] = xv;
    }
}

// ---------------- final out at t=255 ----------------
__global__ void __launch_bounds__(256) outfin_kernel(float* __restrict__ dout) {
    int b = blockIdx.x, j = threadIdx.x;
    float v = g_part[(0 * BATCH + b) * PARTW + j]
            + g_part[(1 * BATCH + b) * PARTW + j]
            + g_part[(2 * BATCH + b) * PARTW + j]
            + g_part[(3 * BATCH + b) * PARTW + j]
            + g_bias[j];
    dout[((size_t)b * TSEQ + (TSEQ - 1)) * DB + j] = sigm(v);
}

// ---------------- host ----------------
extern "C" void kernel_launch(void* const* d_in, const int* in_sizes, int n_in,
                              void* d_out, int out_size) {
    const float* x  = (const float*)d_in[0];
    const float* Wo = (const float*)d_in[1];
    const float* bo = (const float*)d_in[2];
    const float* Ws = (const float*)d_in[3];
    const float* bs = (const float*)d_in[4];
    const float* Wu = (const float*)d_in[5];
    const float* bu = (const float*)d_in[6];
    float* out = (float*)d_out;

    pack_kernel<<<(PARTW * COMBP + 255) / 256, 256>>>(Wo, bo, Ws, bs, Wu, bu);
    init_kernel<<<BATCH, 256>>>(x);
    for (int t = 0; t < TSEQ; t++) {
        gemm_kernel<<<dim3(NCB, KSPLIT), 256>>>();
        if (t < TSEQ - 1) update_kernel<<<256, 256>>>(x, out, t);
    }
    outfin_kernel<<<BATCH, 256>>>(out);
}

// round 15
// speedup vs baseline: 1.0529x; 1.0529x over previous
#include <cuda_runtime.h>
#include <math.h>

// ---------------- problem constants ----------------
#define BATCH 64
#define TSEQ  256
#define INDIM 264
#define SU    512
#define NH    4
#define MSZ   32
#define NA    256
#define DB    256
#define COMBD 904
#define COMBP 1024
#define OUTD  1192
#define UPDD  424
#define HP    106

#define KSPLIT 4
#define KCH    256
#define KSUB   64
#define NCB    38
#define PARTW  1216

// raw upd offsets per head
#define OFF_S     0
#define OFF_JD    3
#define OFF_J     4
#define OFF_GAM   7
#define OFF_ER    8
#define OFF_AD    40
#define OFF_K     72
#define OFF_BETA  104
#define OFF_G     105

#define EPSV 1e-12f

#define MEMSZ (BATCH * MSZ * NA)
#define WTSZ  (BATCH * NH * NA)

// ---------------- device-global scratch ----------------
__device__ float g_Wt[PARTW * COMBP];
__device__ float g_bias[PARTW];
__device__ float g_comb[BATCH * COMBP];
__device__ float g_part[KSPLIT * BATCH * PARTW];
__device__ float g_wt[2 * WTSZ];        // double-buffered by step parity
__device__ float g_wtdyn[WTSZ];
__device__ float g_mem[2 * MEMSZ];      // double-buffered by step parity

__device__ __forceinline__ float sigm(float x) { return 1.0f / (1.0f + __expf(-x)); }
__device__ __forceinline__ float splus(float x) {
    return fmaxf(x, 0.0f) + log1pf(__expf(-fabsf(x)));
}

// packed f32x2 FMA: d = a*b + d (lane-wise on 2 floats in a 64-bit reg)
__device__ __forceinline__ void fma2(unsigned long long& d,
                                     unsigned long long a, unsigned long long b) {
    asm("fma.rn.f32x2 %0, %1, %2, %0;" : "+l"(d) : "l"(a), "l"(b));
}
__device__ __forceinline__ float f2sum(unsigned long long a) {
    float lo, hi;
    asm("mov.b64 {%0, %1}, %2;" : "=f"(lo), "=f"(hi) : "l"(a));
    return lo + hi;
}

// ---------------- weight repack ----------------
__global__ void pack_kernel(const float* __restrict__ Wo, const float* __restrict__ bo,
                            const float* __restrict__ Ws, const float* __restrict__ bs,
                            const float* __restrict__ Wu, const float* __restrict__ bu) {
    int idx = blockIdx.x * 256 + threadIdx.x;
    if (idx < PARTW * COMBP) {
        int j = idx >> 10;
        int k = idx & (COMBP - 1);
        float v = 0.0f;
        if (k < COMBD && j < OUTD) {
            if (j < DB)            v = Wo[k * DB + j];
            else if (j < DB + SU)  v = Ws[k * SU + (j - DB)];
            else                   v = Wu[k * UPDD + (j - DB - SU)];
        }
        g_Wt[idx] = v;
    }
    if (idx < PARTW) {
        g_bias[idx] = (idx >= OUTD) ? 0.0f
                    : (idx < DB) ? bo[idx]
                    : (idx < DB + SU) ? bs[idx - DB]
                    : bu[idx - DB - SU];
    }
}

// ---------------- init: reset carry (parity-0 buffers) + comb_0 ----------------
__global__ void init_kernel(const float* __restrict__ x) {
    int b = blockIdx.x, tid = threadIdx.x;
    for (int i = tid; i < NH * NA; i += 256) {
        float v = ((i & (NA - 1)) == 0) ? 1.0f : 0.0f;
        g_wt[b * NH * NA + i]    = v;
        g_wtdyn[b * NH * NA + i] = v;
    }
    for (int i = tid; i < MSZ * NA; i += 256) g_mem[b * MSZ * NA + i] = 0.01f;
    for (int i = tid; i < COMBP; i += 256) {
        float v;
        if (i < INDIM)            v = x[((size_t)b * TSEQ + 0) * INDIM + i];
        else if (i < INDIM + SU)  v = 1.0f;
        else if (i < COMBD)       v = 0.01f;
        else                      v = 0.0f;
        g_comb[b * COMBP + i] = v;
    }
}

// ---------------- GEMM (f32x2, 4r x 4c per thread, 128 thr): grid (38,4) ----------------
__global__ void __launch_bounds__(128) gemm_kernel() {
    __shared__ float cS[64][KSUB + 4];
    __shared__ float wS[32][KSUB + 4];

    int tid = threadIdx.x;
    int cb = blockIdx.x, ks = blockIdx.y;
    int j0 = cb * 32;
    int k0 = ks * KCH;
    int rq = tid >> 3, cp = tid & 7;   // 16 row-groups x 8 col-slots
    int r0 = rq * 4;

    unsigned long long A[4][4];        // [row][col] packed k-pairs
    #pragma unroll
    for (int i = 0; i < 4; i++)
        #pragma unroll
        for (int c = 0; c < 4; c++) A[i][c] = 0ull;

    float4 cP[8], wP[4];
    {
        int kc = k0;
        #pragma unroll
        for (int s = 0; s < 8; s++) {
            int p = tid + s * 128;     // 1024 f4 (64 rows x 16)
            int r = p >> 4, k4 = p & 15;
            cP[s] = *(const float4*)&g_comb[r * COMBP + kc + 4 * k4];
        }
        #pragma unroll
        for (int s = 0; s < 4; s++) {
            int p = tid + s * 128;     // 512 f4 (32 cols x 16)
            int jj = p >> 4, k4 = p & 15;
            wP[s] = *(const float4*)&g_Wt[(size_t)(j0 + jj) * COMBP + kc + 4 * k4];
        }
    }

    #pragma unroll 1
    for (int sub = 0; sub < KCH / KSUB; sub++) {
        #pragma unroll
        for (int s = 0; s < 8; s++) {
            int p = tid + s * 128;
            int r = p >> 4, k4 = p & 15;
            *(float4*)&cS[r][4 * k4] = cP[s];
        }
        #pragma unroll
        for (int s = 0; s < 4; s++) {
            int p = tid + s * 128;
            int jj = p >> 4, k4 = p & 15;
            *(float4*)&wS[jj][4 * k4] = wP[s];
        }
        __syncthreads();

        if (sub < KCH / KSUB - 1) {
            int kc = k0 + (sub + 1) * KSUB;
            #pragma unroll
            for (int s = 0; s < 8; s++) {
                int p = tid + s * 128;
                int r = p >> 4, k4 = p & 15;
                cP[s] = *(const float4*)&g_comb[r * COMBP + kc + 4 * k4];
            }
            #pragma unroll
            for (int s = 0; s < 4; s++) {
                int p = tid + s * 128;
                int jj = p >> 4, k4 = p & 15;
                wP[s] = *(const float4*)&g_Wt[(size_t)(j0 + jj) * COMBP + kc + 4 * k4];
            }
        }

        #pragma unroll 4
        for (int kk = 0; kk < KSUB; kk += 4) {
            ulonglong2 w0 = *(const ulonglong2*)&wS[cp][kk];
            ulonglong2 w1 = *(const ulonglong2*)&wS[cp + 8][kk];
            ulonglong2 w2 = *(const ulonglong2*)&wS[cp + 16][kk];
            ulonglong2 w3 = *(const ulonglong2*)&wS[cp + 24][kk];
            ulonglong2 q0 = *(const ulonglong2*)&cS[r0 + 0][kk];
            ulonglong2 q1 = *(const ulonglong2*)&cS[r0 + 1][kk];
            ulonglong2 q2 = *(const ulonglong2*)&cS[r0 + 2][kk];
            ulonglong2 q3 = *(const ulonglong2*)&cS[r0 + 3][kk];
            fma2(A[0][0], q0.x, w0.x); fma2(A[0][1], q0.x, w1.x);
            fma2(A[0][2], q0.x, w2.x); fma2(A[0][3], q0.x, w3.x);
            fma2(A[1][0], q1.x, w0.x); fma2(A[1][1], q1.x, w1.x);
            fma2(A[1][2], q1.x, w2.x); fma2(A[1][3], q1.x, w3.x);
            fma2(A[2][0], q2.x, w0.x); fma2(A[2][1], q2.x, w1.x);
            fma2(A[2][2], q2.x, w2.x); fma2(A[2][3], q2.x, w3.x);
            fma2(A[3][0], q3.x, w0.x); fma2(A[3][1], q3.x, w1.x);
            fma2(A[3][2], q3.x, w2.x); fma2(A[3][3], q3.x, w3.x);
            fma2(A[0][0], q0.y, w0.y); fma2(A[0][1], q0.y, w1.y);
            fma2(A[0][2], q0.y, w2.y); fma2(A[0][3], q0.y, w3.y);
            fma2(A[1][0], q1.y, w0.y); fma2(A[1][1], q1.y, w1.y);
            fma2(A[1][2], q1.y, w2.y); fma2(A[1][3], q1.y, w3.y);
            fma2(A[2][0], q2.y, w0.y); fma2(A[2][1], q2.y, w1.y);
            fma2(A[2][2], q2.y, w2.y); fma2(A[2][3], q2.y, w3.y);
            fma2(A[3][0], q3.y, w0.y); fma2(A[3][1], q3.y, w1.y);
            fma2(A[3][2], q3.y, w2.y); fma2(A[3][3], q3.y, w3.y);
        }
        __syncthreads();
    }

    float* pp = &g_part[(ks * BATCH) * PARTW];
    #pragma unroll
    for (int i = 0; i < 4; i++) {
        #pragma unroll
        for (int c = 0; c < 4; c++)
            pp[(r0 + i) * PARTW + j0 + cp + 8 * c] = f2sum(A[i][c]);
    }
}

// ---------------- update: combine + DWM cell; grid=256 (b,h), 256 thr ----------------
// (R13 version — best measured: 10.4 us; do not add instructions here)
__global__ void __launch_bounds__(256) update_kernel(const float* __restrict__ x,
                                                     float* __restrict__ dout, int t) {
    __shared__ float memS[MSZ][260];    // conflict-free row & column access
    __shared__ float wtA[NH * NA];
    __shared__ float wgH[NA];
    __shared__ float wH[NA];
    __shared__ float4 e4v[MSZ], a4v[MSZ];
    __shared__ float pKs[MSZ];
    __shared__ float scl[16];
    __shared__ float red[16];
    __shared__ float upS[HP + 2];

    int b = blockIdx.x >> 2, h = blockIdx.x & 3;
    int tid = threadIdx.x;
    int n = tid, lane = tid & 31, wid = tid >> 5;
    int par = t & 1;

    const float* P0 = &g_part[(0 * BATCH + b) * PARTW];
    const float* P1 = &g_part[(1 * BATCH + b) * PARTW];
    const float* P2 = &g_part[(2 * BATCH + b) * PARTW];
    const float* P3 = &g_part[(3 * BATCH + b) * PARTW];

    float dynOld = g_wtdyn[(b * NH + h) * NA + n];

    // ---- prefetch out/state partials into registers (consumed at tail) ----
    int jOut = 64 * h + tid;               // valid if tid < 64
    int jSt  = 256 + 128 * h + tid;        // valid if tid < 128
    float o0 = 0.f, o1 = 0.f, o2 = 0.f, o3 = 0.f, ob = 0.f;
    float s0 = 0.f, s1 = 0.f, s2 = 0.f, s3 = 0.f, sb = 0.f;
    if (tid < 64) {
        o0 = P0[jOut]; o1 = P1[jOut]; o2 = P2[jOut]; o3 = P3[jOut]; ob = g_bias[jOut];
    }
    if (tid < 128) {
        s0 = P0[jSt]; s1 = P1[jSt]; s2 = P2[jSt]; s3 = P3[jSt]; sb = g_bias[jSt];
    }

    // ---- load mem (8 f4/thread) and all-head wt from parity buffers ----
    const float4* memIn = (const float4*)(g_mem + par * MEMSZ + b * MSZ * NA);
    #pragma unroll
    for (int s = 0; s < 8; s++) {
        int p = tid + s * 256;
        int m = p >> 6, c4 = p & 63;
        *(float4*)&memS[m][4 * c4] = memIn[p];
    }
    *(float4*)&wtA[4 * tid] = ((const float4*)(g_wt + par * WTSZ + b * NH * NA))[tid];

    // ---- own-head raw params ----
    if (tid < HP) {
        int j = 768 + HP * h + tid;
        upS[tid] = P0[j] + P1[j] + P2[j] + P3[j] + g_bias[j];
    }
    // erase/add for ALL heads (needed by the shared memory write)
    {
        int hp = tid >> 6, idx = tid & 63;
        int j = 768 + HP * hp + OFF_ER + idx;
        float v = P0[j] + P1[j] + P2[j] + P3[j] + g_bias[j];
        if (idx < 32) ((float*)&e4v[idx])[hp] = sigm(v);
        else          ((float*)&a4v[idx - 32])[hp] = v;
    }
    __syncthreads();   // S1

    // ---- parse own-head params ----
    if (tid < 32) {
        float kt = tanhf(upS[OFF_K + tid]);
        float ssk = kt * kt;
        #pragma unroll
        for (int o = 16; o; o >>= 1) ssk += __shfl_xor_sync(0xffffffffu, ssk, o);
        pKs[tid] = kt / (sqrtf(ssk) + EPSV);
        if (tid == 0) {
            float q0 = splus(upS[OFF_S + 0]), q1 = splus(upS[OFF_S + 1]), q2 = splus(upS[OFF_S + 2]);
            float mx = fmaxf(q0, fmaxf(q1, q2));
            float e0 = __expf(q0 - mx), e1 = __expf(q1 - mx), e2 = __expf(q2 - mx);
            float inv = 1.0f / (e0 + e1 + e2);
            scl[0] = e0 * inv; scl[1] = e1 * inv; scl[2] = e2 * inv;
            float j0r = upS[OFF_J + 0], j1r = upS[OFF_J + 1], j2r = upS[OFF_J + 2];
            float jm = fmaxf(j0r, fmaxf(j1r, j2r));
            float f0 = __expf(j0r - jm), f1 = __expf(j1r - jm), f2 = __expf(j2r - jm);
            float jinv = 1.0f / (f0 + f1 + f2);
            scl[3] = f0 * jinv; scl[4] = f1 * jinv; scl[5] = f2 * jinv;
            scl[6] = sigm(upS[OFF_JD]);
            scl[7] = 1.0f + splus(upS[OFF_GAM]);
            scl[8] = splus(upS[OFF_BETA]);
            scl[9] = sigm(upS[OFF_G]);
        }
    }

    // ---- memory write (erase, add) — duplicated in 4 head-CTAs; h==0 persists ----
    float4* memOut = (float4*)(g_mem + (par ^ 1) * MEMSZ + b * MSZ * NA);
    #pragma unroll
    for (int s = 0; s < 8; s++) {
        int p = tid + s * 256;
        int m = p >> 6, c4 = p & 63;
        float4 mv = *(const float4*)&memS[m][4 * c4];
        float4 e4 = e4v[m], a4 = a4v[m];
        float4 w0 = *(const float4*)&wtA[0 * 256 + 4 * c4];
        float4 w1 = *(const float4*)&wtA[1 * 256 + 4 * c4];
        float4 w2 = *(const float4*)&wtA[2 * 256 + 4 * c4];
        float4 w3 = *(const float4*)&wtA[3 * 256 + 4 * c4];
        #pragma unroll
        for (int i = 0; i < 4; i++) {
            float vv = (&mv.x)[i];
            float q0 = (&w0.x)[i], q1 = (&w1.x)[i], q2 = (&w2.x)[i], q3 = (&w3.x)[i];
            float prod = (1.0f - e4.x * q0) * (1.0f - e4.y * q1)
                       * (1.0f - e4.z * q2) * (1.0f - e4.w * q3);
            float addv = a4.x * q0 + a4.y * q1 + a4.z * q2 + a4.w * q3;
            (&mv.x)[i] = vv * prod + addv;
        }
        *(float4*)&memS[m][4 * c4] = mv;
        if (h == 0) memOut[p] = mv;
    }
    __syncthreads();   // S2

    // ---- content score: sc = beta * khat . memcol / ||memcol|| ----
    float beta = scl[8], g = scl[9];
    float ss = 0.0f, sc = 0.0f;
    #pragma unroll
    for (int m = 0; m < MSZ; m++) {
        float v = memS[m][n];
        ss = fmaf(v, v, ss);
        sc = fmaf(pKs[m], v, sc);
    }
    sc = sc * beta / (sqrtf(ss) + EPSV);

    // softmax shifted by beta (valid upper bound since cos <= 1)
    float e = __expf(sc - beta);
    float sv = e;
    #pragma unroll
    for (int o = 16; o; o >>= 1) sv += __shfl_xor_sync(0xffffffffu, sv, o);
    if (lane == 0) red[wid] = sv;
    __syncthreads();   // S3
    float tot = red[0] + red[1] + red[2] + red[3] + red[4] + red[5] + red[6] + red[7];
    float wc = e / tot;
    float wOld = wtA[h * 256 + n];
    wgH[n] = fmaf(g, wc - wOld, wOld);
    __syncthreads();   // S4

    // ---- shift + sharpen ----
    float ws = scl[0] * wgH[(n + NA - 1) & (NA - 1)]
             + scl[1] * wgH[n]
             + scl[2] * wgH[(n + 1) & (NA - 1)];
    ws = __expf(scl[7] * __logf(ws + EPSV));
    float sv2 = ws;
    #pragma unroll
    for (int o = 16; o; o >>= 1) sv2 += __shfl_xor_sync(0xffffffffu, sv2, o);
    if (lane == 0) red[8 + wid] = sv2;
    __syncthreads();   // S5
    float tot2 = red[8] + red[9] + red[10] + red[11] + red[12] + red[13] + red[14] + red[15];
    ws /= tot2;

    // ---- snapshot + jump ----
    float jd = scl[6];
    float dynNew = fmaf(jd, ws - dynOld, dynOld);
    g_wtdyn[(b * NH + h) * NA + n] = dynNew;
    float wnew = scl[3] * ws + scl[4] * dynNew + ((n == 0) ? scl[5] : 0.0f);
    g_wt[(par ^ 1) * WTSZ + (b * NH + h) * NA + n] = wnew;
    wH[n] = wnew;
    __syncthreads();   // S6

    // ---- read[h][m] = sum_n wH[n] * memS[m][n] -> comb read segment ----
    {
        int m = tid >> 3, s = tid & 7;
        float acc = 0.0f;
        #pragma unroll
        for (int i = 0; i < 32; i++) {
            int nn = s * 32 + ((i + m + 4 * s) & 31);
            acc = fmaf(wH[nn], memS[m][nn], acc);
        }
        acc += __shfl_down_sync(0xffffffffu, acc, 4, 8);
        acc += __shfl_down_sync(0xffffffffu, acc, 2, 8);
        acc += __shfl_down_sync(0xffffffffu, acc, 1, 8);
        if (s == 0) g_comb[b * COMBP + INDIM + SU + h * 32 + m] = acc;
    }

    // ---- tail: out/state combine (prefetched at top) + x_{t+1} copy ----
    if (tid < 64)
        dout[((size_t)b * TSEQ + t) * DB + jOut] = sigm(o0 + o1 + o2 + o3 + ob);
    if (tid < 128)
        g_comb[b * COMBP + jSt + 8] = sigm(s0 + s1 + s2 + s3 + sb);
    if (h == 0 && tid < 66) {
        float4 xv = *(const float4*)&x[((size_t)b * TSEQ + (t + 1)) * INDIM + 4 * tid];
        *(float4*)&g_comb[b * COMBP + 4 * tid] = xv;
    }
}

// ---------------- final out at t=255 ----------------
__global__ void __launch_bounds__(256) outfin_kernel(float* __restrict__ dout) {
    int b = blockIdx.x, j = threadIdx.x;
    float v = g_part[(0 * BATCH + b) * PARTW + j]
            + g_part[(1 * BATCH + b) * PARTW + j]
            + g_part[(2 * BATCH + b) * PARTW + j]
            + g_part[(3 * BATCH + b) * PARTW + j]
            + g_bias[j];
    dout[((size_t)b * TSEQ + (TSEQ - 1)) * DB + j] = sigm(v);
}

// ---------------- host ----------------
extern "C" void kernel_launch(void* const* d_in, const int* in_sizes, int n_in,
                              void* d_out, int out_size) {
    const float* x  = (const float*)d_in[0];
    const float* Wo = (const float*)d_in[1];
    const float* bo = (const float*)d_in[2];
    const float* Ws = (const float*)d_in[3];
    const float* bs = (const float*)d_in[4];
    const float* Wu = (const float*)d_in[5];
    const float* bu = (const float*)d_in[6];
    float* out = (float*)d_out;

    pack_kernel<<<(PARTW * COMBP + 255) / 256, 256>>>(Wo, bo, Ws, bs, Wu, bu);
    init_kernel<<<BATCH, 256>>>(x);
    for (int t = 0; t < TSEQ; t++) {
        gemm_kernel<<<dim3(NCB, KSPLIT), 128>>>();
        if (t < TSEQ - 1) update_kernel<<<256, 256>>>(x, out, t);
    }
    outfin_kernel<<<BATCH, 256>>>(out);
}